// round 2
// baseline (speedup 1.0000x reference)
#include <cuda_runtime.h>
#include <cuda_bf16.h>
#include <cstdint>

// Problem constants (fixed by the dataset)
#define M_ROWS 1024     // B*T_NEW
#define CDIM   2048
#define HHEADS 16
#define DHEAD  128
#define TPAST  2048
#define TNEW   128
#define TTOT   2176
#define BATCH  8

// Scratch (no cudaMalloc allowed)
__device__ float g_Q[M_ROWS * CDIM];
__device__ float g_attn[M_ROWS * CDIM];

__device__ __forceinline__ float tf32r(float x) {
    float y;
    asm("cvt.rna.tf32.f32 %0, %1;" : "=f"(y) : "f"(x));
    return y;
}

__device__ __forceinline__ void mma8(float* c, const float* a, const float* b) {
    const uint32_t* A = reinterpret_cast<const uint32_t*>(a);
    const uint32_t* B = reinterpret_cast<const uint32_t*>(b);
    asm volatile(
        "mma.sync.aligned.m16n8k8.row.col.f32.tf32.tf32.f32 "
        "{%0,%1,%2,%3}, {%4,%5,%6,%7}, {%8,%9}, {%0,%1,%2,%3};\n"
        : "+f"(c[0]), "+f"(c[1]), "+f"(c[2]), "+f"(c[3])
        : "r"(A[0]), "r"(A[1]), "r"(A[2]), "r"(A[3]), "r"(B[0]), "r"(B[1]));
}

// ---------------------------------------------------------------------------
// Tiled tf32 GEMM: out = A(1024x2048) @ W(2048x2048) + bias
// scatter=0: out[row*2048+col]
// scatter=1: split-heads scatter into KV concat: out[((b*16+h)*2176+2048+t)*128+d]
// ---------------------------------------------------------------------------
__global__ __launch_bounds__(256) void gemm_tf32(
    const float* __restrict__ A, const float* __restrict__ W,
    const float* __restrict__ bias, float* __restrict__ out, int scatter)
{
    __shared__ float sA[128][33];
    __shared__ float sB[32][129];

    int tid = threadIdx.x;
    int lane = tid & 31, wid = tid >> 5;
    int g = lane >> 2, tg = lane & 3;
    int wr = (wid >> 2) * 64;  // warp row offset within block (0/64)
    int wc = (wid & 3) * 32;   // warp col offset within block
    int bm = blockIdx.y * 128;
    int bn = blockIdx.x * 128;

    float acc[4][4][4];
#pragma unroll
    for (int i = 0; i < 4; i++)
#pragma unroll
        for (int j = 0; j < 4; j++)
#pragma unroll
            for (int k = 0; k < 4; k++) acc[i][j][k] = 0.f;

    for (int kt = 0; kt < CDIM; kt += 32) {
#pragma unroll
        for (int i = 0; i < 4; i++) {
            int f = tid + i * 256;
            int r = f >> 3, c4 = (f & 7) * 4;
            float4 v = *reinterpret_cast<const float4*>(&A[(bm + r) * CDIM + kt + c4]);
            sA[r][c4 + 0] = tf32r(v.x); sA[r][c4 + 1] = tf32r(v.y);
            sA[r][c4 + 2] = tf32r(v.z); sA[r][c4 + 3] = tf32r(v.w);
        }
#pragma unroll
        for (int i = 0; i < 4; i++) {
            int f = tid + i * 256;
            int r = f >> 5, c4 = (f & 31) * 4;
            float4 v = *reinterpret_cast<const float4*>(&W[(kt + r) * CDIM + bn + c4]);
            sB[r][c4 + 0] = tf32r(v.x); sB[r][c4 + 1] = tf32r(v.y);
            sB[r][c4 + 2] = tf32r(v.z); sB[r][c4 + 3] = tf32r(v.w);
        }
        __syncthreads();

#pragma unroll
        for (int ks = 0; ks < 4; ks++) {
            float a[4][4], b[4][2];
#pragma unroll
            for (int mi = 0; mi < 4; mi++) {
                int r = wr + mi * 16;
                a[mi][0] = sA[r + g][ks * 8 + tg];
                a[mi][1] = sA[r + g + 8][ks * 8 + tg];
                a[mi][2] = sA[r + g][ks * 8 + tg + 4];
                a[mi][3] = sA[r + g + 8][ks * 8 + tg + 4];
            }
#pragma unroll
            for (int ni = 0; ni < 4; ni++) {
                int cn = wc + ni * 8 + g;
                b[ni][0] = sB[ks * 8 + tg][cn];
                b[ni][1] = sB[ks * 8 + tg + 4][cn];
            }
#pragma unroll
            for (int mi = 0; mi < 4; mi++)
#pragma unroll
                for (int ni = 0; ni < 4; ni++)
                    mma8(acc[mi][ni], a[mi], b[ni]);
        }
        __syncthreads();
    }

#pragma unroll
    for (int mi = 0; mi < 4; mi++) {
#pragma unroll
        for (int ni = 0; ni < 4; ni++) {
            int row0 = bm + wr + mi * 16 + g;
            int col0 = bn + wc + ni * 8 + 2 * tg;
#pragma unroll
            for (int e = 0; e < 4; e++) {
                int row = row0 + ((e >= 2) ? 8 : 0);
                int col = col0 + (e & 1);
                float v = acc[mi][ni][e] + bias[col];
                if (!scatter) {
                    out[row * CDIM + col] = v;
                } else {
                    int b_ = row >> 7, t_ = row & 127;
                    int h_ = col >> 7, d_ = col & 127;
                    out[((b_ * HHEADS + h_) * TTOT + TPAST + t_) * DHEAD + d_] = v;
                }
            }
        }
    }
}

// ---------------------------------------------------------------------------
// Copy K_past/V_past into the concat output slabs
// grid: (256, 128 slabs, 2 tensors), block 256, float4 per thread
// ---------------------------------------------------------------------------
__global__ void copy_past_kernel(const float4* __restrict__ Ks, const float4* __restrict__ Vs,
                                 float4* __restrict__ Kd, float4* __restrict__ Vd)
{
    int slab = blockIdx.y;
    int i = blockIdx.x * blockDim.x + threadIdx.x;  // 0..65535
    const float4* s = blockIdx.z ? Vs : Ks;
    float4* d = blockIdx.z ? Vd : Kd;
    d[(size_t)slab * (TTOT * DHEAD / 4) + i] = s[(size_t)slab * (TPAST * DHEAD / 4) + i];
}

// ---------------------------------------------------------------------------
// Flash attention: one CTA per (b,h). 8 warps, each owns 16 query rows.
// S = (Q*scale) K^T via tf32 mma, online softmax, O += P V via tf32 mma.
// ---------------------------------------------------------------------------
#define SMS 132  // padded smem row stride (floats)

__global__ __launch_bounds__(256) void attn_kernel(
    const float* __restrict__ Kc, const float* __restrict__ Vc)
{
    extern __shared__ float sm[];
    float* sQ = sm;                  // [128][SMS]
    float* sK = sm + 128 * SMS;      // K tile, then reused for P
    float* sV = sm + 2 * 128 * SMS;  // V tile

    int tid = threadIdx.x, lane = tid & 31, wid = tid >> 5;
    int g = lane >> 2, tg = lane & 3;
    int bh = blockIdx.x, b = bh >> 4, h = bh & 15;
    const float qscale = 0.08838834764831845f;  // 1/sqrt(128)

    // Load Q tile (scaled, tf32-rounded)
#pragma unroll
    for (int i = 0; i < 16; i++) {
        int f = tid + i * 256;
        int r = f >> 5, c4 = (f & 31) * 4;
        float4 v = *reinterpret_cast<const float4*>(&g_Q[(b * TNEW + r) * CDIM + h * DHEAD + c4]);
        sQ[r * SMS + c4 + 0] = tf32r(v.x * qscale);
        sQ[r * SMS + c4 + 1] = tf32r(v.y * qscale);
        sQ[r * SMS + c4 + 2] = tf32r(v.z * qscale);
        sQ[r * SMS + c4 + 3] = tf32r(v.w * qscale);
    }

    int r0 = wid * 16;
    float m0 = -1e30f, m1 = -1e30f, l0 = 0.f, l1 = 0.f;
    float O[16][4];
#pragma unroll
    for (int nt = 0; nt < 16; nt++)
#pragma unroll
        for (int e = 0; e < 4; e++) O[nt][e] = 0.f;

    const float* Kbh = Kc + (size_t)bh * TTOT * DHEAD;
    const float* Vbh = Vc + (size_t)bh * TTOT * DHEAD;

    for (int kt = 0; kt < 17; kt++) {
        // Load K tile
#pragma unroll
        for (int i = 0; i < 16; i++) {
            int f = tid + i * 256;
            int r = f >> 5, c4 = (f & 31) * 4;
            float4 v = *reinterpret_cast<const float4*>(&Kbh[(kt * 128 + r) * DHEAD + c4]);
            sK[r * SMS + c4 + 0] = tf32r(v.x);
            sK[r * SMS + c4 + 1] = tf32r(v.y);
            sK[r * SMS + c4 + 2] = tf32r(v.z);
            sK[r * SMS + c4 + 3] = tf32r(v.w);
        }
        __syncthreads();

        // S = Q K^T  (16 rows x 128 keys per warp)
        float S[16][4];
#pragma unroll
        for (int nt = 0; nt < 16; nt++)
#pragma unroll
            for (int e = 0; e < 4; e++) S[nt][e] = 0.f;

#pragma unroll
        for (int ks = 0; ks < 16; ks++) {
            float a[4];
            a[0] = sQ[(r0 + g) * SMS + ks * 8 + tg];
            a[1] = sQ[(r0 + g + 8) * SMS + ks * 8 + tg];
            a[2] = sQ[(r0 + g) * SMS + ks * 8 + tg + 4];
            a[3] = sQ[(r0 + g + 8) * SMS + ks * 8 + tg + 4];
#pragma unroll
            for (int nt = 0; nt < 16; nt++) {
                float bb[2];
                bb[0] = sK[(nt * 8 + g) * SMS + ks * 8 + tg];
                bb[1] = sK[(nt * 8 + g) * SMS + ks * 8 + tg + 4];
                mma8(S[nt], a, bb);
            }
        }

        // Causal mask on the last tile (new keys): key col > query row -> -inf
        if (kt == 16) {
            int q0 = r0 + g, q1 = r0 + g + 8;
#pragma unroll
            for (int nt = 0; nt < 16; nt++) {
                int c0 = nt * 8 + 2 * tg;
                if (c0 > q0) S[nt][0] = -1e30f;
                if (c0 + 1 > q0) S[nt][1] = -1e30f;
                if (c0 > q1) S[nt][2] = -1e30f;
                if (c0 + 1 > q1) S[nt][3] = -1e30f;
            }
        }

        // Online softmax update
        float mx0 = -1e30f, mx1 = -1e30f;
#pragma unroll
        for (int nt = 0; nt < 16; nt++) {
            mx0 = fmaxf(mx0, fmaxf(S[nt][0], S[nt][1]));
            mx1 = fmaxf(mx1, fmaxf(S[nt][2], S[nt][3]));
        }
        mx0 = fmaxf(mx0, __shfl_xor_sync(0xffffffffu, mx0, 1));
        mx0 = fmaxf(mx0, __shfl_xor_sync(0xffffffffu, mx0, 2));
        mx1 = fmaxf(mx1, __shfl_xor_sync(0xffffffffu, mx1, 1));
        mx1 = fmaxf(mx1, __shfl_xor_sync(0xffffffffu, mx1, 2));

        float mn0 = fmaxf(m0, mx0), mn1 = fmaxf(m1, mx1);
        float sc0 = __expf(m0 - mn0), sc1 = __expf(m1 - mn1);
        float rs0 = 0.f, rs1 = 0.f;
#pragma unroll
        for (int nt = 0; nt < 16; nt++) {
            S[nt][0] = __expf(S[nt][0] - mn0);
            S[nt][1] = __expf(S[nt][1] - mn0);
            S[nt][2] = __expf(S[nt][2] - mn1);
            S[nt][3] = __expf(S[nt][3] - mn1);
            rs0 += S[nt][0] + S[nt][1];
            rs1 += S[nt][2] + S[nt][3];
        }
        rs0 += __shfl_xor_sync(0xffffffffu, rs0, 1);
        rs0 += __shfl_xor_sync(0xffffffffu, rs0, 2);
        rs1 += __shfl_xor_sync(0xffffffffu, rs1, 1);
        rs1 += __shfl_xor_sync(0xffffffffu, rs1, 2);

        l0 = l0 * sc0 + rs0;
        l1 = l1 * sc1 + rs1;
#pragma unroll
        for (int nt = 0; nt < 16; nt++) {
            O[nt][0] *= sc0; O[nt][1] *= sc0;
            O[nt][2] *= sc1; O[nt][3] *= sc1;
        }
        m0 = mn0; m1 = mn1;

        __syncthreads();  // all warps done reading sK

        // Write P into sK (reuse), cooperatively load V tile
#pragma unroll
        for (int nt = 0; nt < 16; nt++) {
            sK[(r0 + g) * SMS + nt * 8 + 2 * tg]         = tf32r(S[nt][0]);
            sK[(r0 + g) * SMS + nt * 8 + 2 * tg + 1]     = tf32r(S[nt][1]);
            sK[(r0 + g + 8) * SMS + nt * 8 + 2 * tg]     = tf32r(S[nt][2]);
            sK[(r0 + g + 8) * SMS + nt * 8 + 2 * tg + 1] = tf32r(S[nt][3]);
        }
#pragma unroll
        for (int i = 0; i < 16; i++) {
            int f = tid + i * 256;
            int r = f >> 5, c4 = (f & 31) * 4;
            float4 v = *reinterpret_cast<const float4*>(&Vbh[(kt * 128 + r) * DHEAD + c4]);
            sV[r * SMS + c4 + 0] = tf32r(v.x);
            sV[r * SMS + c4 + 1] = tf32r(v.y);
            sV[r * SMS + c4 + 2] = tf32r(v.z);
            sV[r * SMS + c4 + 3] = tf32r(v.w);
        }
        __syncthreads();

        // O += P V
#pragma unroll
        for (int ks = 0; ks < 16; ks++) {
            float a[4];
            a[0] = sK[(r0 + g) * SMS + ks * 8 + tg];
            a[1] = sK[(r0 + g + 8) * SMS + ks * 8 + tg];
            a[2] = sK[(r0 + g) * SMS + ks * 8 + tg + 4];
            a[3] = sK[(r0 + g + 8) * SMS + ks * 8 + tg + 4];
#pragma unroll
            for (int nt = 0; nt < 16; nt++) {
                float bb[2];
                bb[0] = sV[(ks * 8 + tg) * SMS + nt * 8 + g];
                bb[1] = sV[(ks * 8 + tg + 4) * SMS + nt * 8 + g];
                mma8(O[nt], a, bb);
            }
        }
        __syncthreads();  // before next iteration overwrites sK/sV
    }

    float i0 = 1.f / l0, i1 = 1.f / l1;
#pragma unroll
    for (int nt = 0; nt < 16; nt++) {
        int col = h * DHEAD + nt * 8 + 2 * tg;
        float* o0 = &g_attn[(b * TNEW + r0 + g) * CDIM + col];
        o0[0] = O[nt][0] * i0;
        o0[1] = O[nt][1] * i0;
        float* o1 = &g_attn[(b * TNEW + r0 + g + 8) * CDIM + col];
        o1[0] = O[nt][2] * i1;
        o1[1] = O[nt][3] * i1;
    }
}

// ---------------------------------------------------------------------------
extern "C" void kernel_launch(void* const* d_in, const int* in_sizes, int n_in,
                              void* d_out, int out_size)
{
    const float* x  = (const float*)d_in[0];
    const float* Kp = (const float*)d_in[1];
    const float* Vp = (const float*)d_in[2];
    const float* Wq = (const float*)d_in[3];
    const float* bq = (const float*)d_in[4];
    const float* Wk = (const float*)d_in[5];
    const float* bk = (const float*)d_in[6];
    const float* Wv = (const float*)d_in[7];
    const float* bv = (const float*)d_in[8];
    const float* Wo = (const float*)d_in[9];
    const float* bo = (const float*)d_in[10];

    float* out  = (float*)d_out;
    float* Kout = out + (size_t)M_ROWS * CDIM;                     // 2,097,152
    float* Vout = Kout + (size_t)BATCH * HHEADS * TTOT * DHEAD;    // +35,651,584

    float *gQ, *gA;
    cudaGetSymbolAddress((void**)&gQ, g_Q);
    cudaGetSymbolAddress((void**)&gA, g_attn);

    const int attn_smem = 3 * 128 * SMS * sizeof(float);  // 202,752 B
    cudaFuncSetAttribute(attn_kernel, cudaFuncAttributeMaxDynamicSharedMemorySize, attn_smem);

    dim3 cg(TPAST * DHEAD / 4 / 256, BATCH * HHEADS, 2);  // (256,128,2)
    copy_past_kernel<<<cg, 256>>>((const float4*)Kp, (const float4*)Vp,
                                  (float4*)Kout, (float4*)Vout);

    dim3 gg(CDIM / 128, M_ROWS / 128);  // (16, 8)
    gemm_tf32<<<gg, 256>>>(x, Wq, bq, gQ, 0);
    gemm_tf32<<<gg, 256>>>(x, Wk, bk, Kout, 1);
    gemm_tf32<<<gg, 256>>>(x, Wv, bv, Vout, 1);

    attn_kernel<<<BATCH * HHEADS, 256, attn_smem>>>(Kout, Vout);

    gemm_tf32<<<gg, 256>>>(gA, Wo, bo, out, 0);
}

// round 3
// speedup vs baseline: 1.6480x; 1.6480x over previous
#include <cuda_runtime.h>
#include <cuda_bf16.h>
#include <cstdint>

// Problem constants (fixed by the dataset)
#define M_ROWS 1024     // B*T_NEW
#define CDIM   2048
#define HHEADS 16
#define DHEAD  128
#define TPAST  2048
#define TNEW   128
#define TTOT   2176
#define BATCH  8

#define SA_STRIDE 40    // permuted-k A tile row stride (floats) -> conflict-free LDS.64
#define SB_STRIDE 136   // B tile row stride (floats) -> conflict-free scalar b-frag LDS

// Scratch (no cudaMalloc allowed)
__device__ float g_Q[M_ROWS * CDIM];
__device__ float g_attn[M_ROWS * CDIM];

__device__ __forceinline__ float tf32r(float x) {
    float y;
    asm("cvt.rna.tf32.f32 %0, %1;" : "=f"(y) : "f"(x));
    return y;
}

__device__ __forceinline__ void mma8(float* c, const float* a, const float* b) {
    const uint32_t* A = reinterpret_cast<const uint32_t*>(a);
    const uint32_t* B = reinterpret_cast<const uint32_t*>(b);
    asm volatile(
        "mma.sync.aligned.m16n8k8.row.col.f32.tf32.tf32.f32 "
        "{%0,%1,%2,%3}, {%4,%5,%6,%7}, {%8,%9}, {%0,%1,%2,%3};\n"
        : "+f"(c[0]), "+f"(c[1]), "+f"(c[2]), "+f"(c[3])
        : "r"(A[0]), "r"(A[1]), "r"(A[2]), "r"(A[3]), "r"(B[0]), "r"(B[1]));
}

// ---------------------------------------------------------------------------
// GEMM core: out(128x128 tile at bm,bn) = A(1024x2048) @ W(2048x2048) + bias
// Register-double-buffered global loads; permuted-k A layout for LDS.64 frags.
// scatter=0: out[row*2048+col]
// scatter=1: split-heads scatter into KV concat slot
// ---------------------------------------------------------------------------
__device__ __forceinline__ void gemm_core(
    const float* __restrict__ A, const float* __restrict__ W,
    const float* __restrict__ bias, float* __restrict__ out,
    int scatter, int bm, int bn, float* sA, float* sB)
{
    int tid = threadIdx.x;
    int lane = tid & 31, wid = tid >> 5;
    int g = lane >> 2, tg = lane & 3;
    int wr = (wid >> 2) * 64;  // warp row offset (0/64)
    int wc = (wid & 3) * 32;   // warp col offset

    float acc[4][4][4];
#pragma unroll
    for (int i = 0; i < 4; i++)
#pragma unroll
        for (int j = 0; j < 4; j++)
#pragma unroll
            for (int k = 0; k < 4; k++) acc[i][j][k] = 0.f;

    // per-thread load geometry
    //   A: f = tid + i*256 -> row f>>3, cols (f&7)*4 .. +3   (8 float4 per row)
    //   B: f = tid + i*256 -> krow f>>5, cols (f&31)*4 .. +3
    float4 ra[4], rb[4];

#pragma unroll
    for (int i = 0; i < 4; i++) {
        int f = tid + i * 256;
        ra[i] = *reinterpret_cast<const float4*>(&A[(bm + (f >> 3)) * CDIM + (f & 7) * 4]);
        rb[i] = *reinterpret_cast<const float4*>(&W[(f >> 5) * CDIM + bn + (f & 31) * 4]);
    }

    for (int kt = 0; kt < CDIM; kt += 32) {
        // store prefetched tile to smem (tf32-rounded)
#pragma unroll
        for (int i = 0; i < 4; i++) {
            int f = tid + i * 256;
            int r = f >> 3, c4 = (f & 7) * 4;
            float v[4] = {tf32r(ra[i].x), tf32r(ra[i].y), tf32r(ra[i].z), tf32r(ra[i].w)};
#pragma unroll
            for (int j = 0; j < 4; j++) {
                int k = c4 + j;
                int p = (k >> 3) * 8 + (k & 3) * 2 + ((k >> 2) & 1);  // permuted-k
                sA[r * SA_STRIDE + p] = v[j];
            }
        }
#pragma unroll
        for (int i = 0; i < 4; i++) {
            int f = tid + i * 256;
            int kr = f >> 5, c4 = (f & 31) * 4;
            float4 v;
            v.x = tf32r(rb[i].x); v.y = tf32r(rb[i].y);
            v.z = tf32r(rb[i].z); v.w = tf32r(rb[i].w);
            *reinterpret_cast<float4*>(&sB[kr * SB_STRIDE + c4]) = v;
        }
        __syncthreads();

        // prefetch next tile
        if (kt + 32 < CDIM) {
#pragma unroll
            for (int i = 0; i < 4; i++) {
                int f = tid + i * 256;
                ra[i] = *reinterpret_cast<const float4*>(
                    &A[(bm + (f >> 3)) * CDIM + kt + 32 + (f & 7) * 4]);
                rb[i] = *reinterpret_cast<const float4*>(
                    &W[(kt + 32 + (f >> 5)) * CDIM + bn + (f & 31) * 4]);
            }
        }

        // compute 4 k8-steps
#pragma unroll
        for (int ks = 0; ks < 4; ks++) {
            float2 a2[4][2];
#pragma unroll
            for (int mi = 0; mi < 4; mi++) {
                int r = wr + mi * 16;
                a2[mi][0] = *reinterpret_cast<const float2*>(
                    &sA[(r + g) * SA_STRIDE + ks * 8 + 2 * tg]);       // {a0,a2}
                a2[mi][1] = *reinterpret_cast<const float2*>(
                    &sA[(r + g + 8) * SA_STRIDE + ks * 8 + 2 * tg]);   // {a1,a3}
            }
            float b[4][2];
#pragma unroll
            for (int ni = 0; ni < 4; ni++) {
                int cn = wc + ni * 8 + g;
                b[ni][0] = sB[(ks * 8 + tg) * SB_STRIDE + cn];
                b[ni][1] = sB[(ks * 8 + tg + 4) * SB_STRIDE + cn];
            }
#pragma unroll
            for (int mi = 0; mi < 4; mi++) {
                float a[4] = {a2[mi][0].x, a2[mi][1].x, a2[mi][0].y, a2[mi][1].y};
#pragma unroll
                for (int ni = 0; ni < 4; ni++)
                    mma8(acc[mi][ni], a, b[ni]);
            }
        }
        __syncthreads();
    }

#pragma unroll
    for (int mi = 0; mi < 4; mi++) {
#pragma unroll
        for (int ni = 0; ni < 4; ni++) {
            int row0 = bm + wr + mi * 16 + g;
            int col0 = bn + wc + ni * 8 + 2 * tg;
#pragma unroll
            for (int e = 0; e < 4; e++) {
                int row = row0 + ((e >= 2) ? 8 : 0);
                int col = col0 + (e & 1);
                float v = acc[mi][ni][e] + bias[col];
                if (!scatter) {
                    out[row * CDIM + col] = v;
                } else {
                    int b_ = row >> 7, t_ = row & 127;
                    int h_ = col >> 7, d_ = col & 127;
                    out[((b_ * HHEADS + h_) * TTOT + TPAST + t_) * DHEAD + d_] = v;
                }
            }
        }
    }
}

// ---------------------------------------------------------------------------
// Fused: z=0..2 -> Q/K/V projections; z=3 -> past-KV copy (overlapped)
// ---------------------------------------------------------------------------
__global__ __launch_bounds__(256, 1) void fused_qkv_copy(
    const float* __restrict__ x,
    const float* __restrict__ Wq, const float* __restrict__ bq,
    const float* __restrict__ Wk, const float* __restrict__ bk,
    const float* __restrict__ Wv, const float* __restrict__ bv,
    const float* __restrict__ Kp, const float* __restrict__ Vp,
    float* __restrict__ gQ, float* __restrict__ Kout, float* __restrict__ Vout)
{
    __shared__ __align__(16) float smem[128 * SA_STRIDE + 32 * SB_STRIDE];
    int z = blockIdx.z;

    if (z == 3) {
        // past copy: one block per (b,h) slab, copies K and V interleaved
        int slab = blockIdx.y * 16 + blockIdx.x;  // 0..127
        const float4* Ks = reinterpret_cast<const float4*>(Kp) + (size_t)slab * (TPAST * DHEAD / 4);
        const float4* Vs = reinterpret_cast<const float4*>(Vp) + (size_t)slab * (TPAST * DHEAD / 4);
        float4* Kd = reinterpret_cast<float4*>(Kout) + (size_t)slab * (TTOT * DHEAD / 4);
        float4* Vd = reinterpret_cast<float4*>(Vout) + (size_t)slab * (TTOT * DHEAD / 4);
        for (int i = threadIdx.x; i < TPAST * DHEAD / 4; i += 256) {
            Kd[i] = Ks[i];
            Vd[i] = Vs[i];
        }
        return;
    }

    int bm = blockIdx.y * 128, bn = blockIdx.x * 128;
    float* sA = smem;
    float* sB = smem + 128 * SA_STRIDE;
    if (z == 0)      gemm_core(x, Wq, bq, gQ,   0, bm, bn, sA, sB);
    else if (z == 1) gemm_core(x, Wk, bk, Kout, 1, bm, bn, sA, sB);
    else             gemm_core(x, Wv, bv, Vout, 1, bm, bn, sA, sB);
}

__global__ __launch_bounds__(256, 1) void gemm_wo(
    const float* __restrict__ A, const float* __restrict__ W,
    const float* __restrict__ bias, float* __restrict__ out)
{
    __shared__ __align__(16) float smem[128 * SA_STRIDE + 32 * SB_STRIDE];
    gemm_core(A, W, bias, out, 0, blockIdx.y * 128, blockIdx.x * 128,
              smem, smem + 128 * SA_STRIDE);
}

// ---------------------------------------------------------------------------
// Flash attention: one CTA per (b,h). 8 warps, each owns 16 query rows.
// ---------------------------------------------------------------------------
#define SMS 132  // padded smem row stride (floats)

__global__ __launch_bounds__(256) void attn_kernel(
    const float* __restrict__ Kc, const float* __restrict__ Vc)
{
    extern __shared__ float sm[];
    float* sQ = sm;                  // [128][SMS]
    float* sK = sm + 128 * SMS;      // K tile, then reused for P
    float* sV = sm + 2 * 128 * SMS;  // V tile

    int tid = threadIdx.x, lane = tid & 31, wid = tid >> 5;
    int g = lane >> 2, tg = lane & 3;
    int bh = blockIdx.x, b = bh >> 4, h = bh & 15;
    const float qscale = 0.08838834764831845f;  // 1/sqrt(128)

#pragma unroll
    for (int i = 0; i < 16; i++) {
        int f = tid + i * 256;
        int r = f >> 5, c4 = (f & 31) * 4;
        float4 v = *reinterpret_cast<const float4*>(&g_Q[(b * TNEW + r) * CDIM + h * DHEAD + c4]);
        sQ[r * SMS + c4 + 0] = tf32r(v.x * qscale);
        sQ[r * SMS + c4 + 1] = tf32r(v.y * qscale);
        sQ[r * SMS + c4 + 2] = tf32r(v.z * qscale);
        sQ[r * SMS + c4 + 3] = tf32r(v.w * qscale);
    }

    int r0 = wid * 16;
    float m0 = -1e30f, m1 = -1e30f, l0 = 0.f, l1 = 0.f;
    float O[16][4];
#pragma unroll
    for (int nt = 0; nt < 16; nt++)
#pragma unroll
        for (int e = 0; e < 4; e++) O[nt][e] = 0.f;

    const float* Kbh = Kc + (size_t)bh * TTOT * DHEAD;
    const float* Vbh = Vc + (size_t)bh * TTOT * DHEAD;

    for (int kt = 0; kt < 17; kt++) {
#pragma unroll
        for (int i = 0; i < 16; i++) {
            int f = tid + i * 256;
            int r = f >> 5, c4 = (f & 31) * 4;
            float4 v = *reinterpret_cast<const float4*>(&Kbh[(kt * 128 + r) * DHEAD + c4]);
            sK[r * SMS + c4 + 0] = tf32r(v.x);
            sK[r * SMS + c4 + 1] = tf32r(v.y);
            sK[r * SMS + c4 + 2] = tf32r(v.z);
            sK[r * SMS + c4 + 3] = tf32r(v.w);
        }
        __syncthreads();

        float S[16][4];
#pragma unroll
        for (int nt = 0; nt < 16; nt++)
#pragma unroll
            for (int e = 0; e < 4; e++) S[nt][e] = 0.f;

#pragma unroll
        for (int ks = 0; ks < 16; ks++) {
            float a[4];
            a[0] = sQ[(r0 + g) * SMS + ks * 8 + tg];
            a[1] = sQ[(r0 + g + 8) * SMS + ks * 8 + tg];
            a[2] = sQ[(r0 + g) * SMS + ks * 8 + tg + 4];
            a[3] = sQ[(r0 + g + 8) * SMS + ks * 8 + tg + 4];
#pragma unroll
            for (int nt = 0; nt < 16; nt++) {
                float bb[2];
                bb[0] = sK[(nt * 8 + g) * SMS + ks * 8 + tg];
                bb[1] = sK[(nt * 8 + g) * SMS + ks * 8 + tg + 4];
                mma8(S[nt], a, bb);
            }
        }

        if (kt == 16) {
            int q0 = r0 + g, q1 = r0 + g + 8;
#pragma unroll
            for (int nt = 0; nt < 16; nt++) {
                int c0 = nt * 8 + 2 * tg;
                if (c0 > q0) S[nt][0] = -1e30f;
                if (c0 + 1 > q0) S[nt][1] = -1e30f;
                if (c0 > q1) S[nt][2] = -1e30f;
                if (c0 + 1 > q1) S[nt][3] = -1e30f;
            }
        }

        float mx0 = -1e30f, mx1 = -1e30f;
#pragma unroll
        for (int nt = 0; nt < 16; nt++) {
            mx0 = fmaxf(mx0, fmaxf(S[nt][0], S[nt][1]));
            mx1 = fmaxf(mx1, fmaxf(S[nt][2], S[nt][3]));
        }
        mx0 = fmaxf(mx0, __shfl_xor_sync(0xffffffffu, mx0, 1));
        mx0 = fmaxf(mx0, __shfl_xor_sync(0xffffffffu, mx0, 2));
        mx1 = fmaxf(mx1, __shfl_xor_sync(0xffffffffu, mx1, 1));
        mx1 = fmaxf(mx1, __shfl_xor_sync(0xffffffffu, mx1, 2));

        float mn0 = fmaxf(m0, mx0), mn1 = fmaxf(m1, mx1);
        float sc0 = __expf(m0 - mn0), sc1 = __expf(m1 - mn1);
        float rs0 = 0.f, rs1 = 0.f;
#pragma unroll
        for (int nt = 0; nt < 16; nt++) {
            S[nt][0] = __expf(S[nt][0] - mn0);
            S[nt][1] = __expf(S[nt][1] - mn0);
            S[nt][2] = __expf(S[nt][2] - mn1);
            S[nt][3] = __expf(S[nt][3] - mn1);
            rs0 += S[nt][0] + S[nt][1];
            rs1 += S[nt][2] + S[nt][3];
        }
        rs0 += __shfl_xor_sync(0xffffffffu, rs0, 1);
        rs0 += __shfl_xor_sync(0xffffffffu, rs0, 2);
        rs1 += __shfl_xor_sync(0xffffffffu, rs1, 1);
        rs1 += __shfl_xor_sync(0xffffffffu, rs1, 2);

        l0 = l0 * sc0 + rs0;
        l1 = l1 * sc1 + rs1;
#pragma unroll
        for (int nt = 0; nt < 16; nt++) {
            O[nt][0] *= sc0; O[nt][1] *= sc0;
            O[nt][2] *= sc1; O[nt][3] *= sc1;
        }
        m0 = mn0; m1 = mn1;

        __syncthreads();

#pragma unroll
        for (int nt = 0; nt < 16; nt++) {
            sK[(r0 + g) * SMS + nt * 8 + 2 * tg]         = tf32r(S[nt][0]);
            sK[(r0 + g) * SMS + nt * 8 + 2 * tg + 1]     = tf32r(S[nt][1]);
            sK[(r0 + g + 8) * SMS + nt * 8 + 2 * tg]     = tf32r(S[nt][2]);
            sK[(r0 + g + 8) * SMS + nt * 8 + 2 * tg + 1] = tf32r(S[nt][3]);
        }
#pragma unroll
        for (int i = 0; i < 16; i++) {
            int f = tid + i * 256;
            int r = f >> 5, c4 = (f & 31) * 4;
            float4 v = *reinterpret_cast<const float4*>(&Vbh[(kt * 128 + r) * DHEAD + c4]);
            sV[r * SMS + c4 + 0] = tf32r(v.x);
            sV[r * SMS + c4 + 1] = tf32r(v.y);
            sV[r * SMS + c4 + 2] = tf32r(v.z);
            sV[r * SMS + c4 + 3] = tf32r(v.w);
        }
        __syncthreads();

#pragma unroll
        for (int ks = 0; ks < 16; ks++) {
            float a[4];
            a[0] = sK[(r0 + g) * SMS + ks * 8 + tg];
            a[1] = sK[(r0 + g + 8) * SMS + ks * 8 + tg];
            a[2] = sK[(r0 + g) * SMS + ks * 8 + tg + 4];
            a[3] = sK[(r0 + g + 8) * SMS + ks * 8 + tg + 4];
#pragma unroll
            for (int nt = 0; nt < 16; nt++) {
                float bb[2];
                bb[0] = sV[(ks * 8 + tg) * SMS + nt * 8 + g];
                bb[1] = sV[(ks * 8 + tg + 4) * SMS + nt * 8 + g];
                mma8(O[nt], a, bb);
            }
        }
        __syncthreads();
    }

    float i0 = 1.f / l0, i1 = 1.f / l1;
#pragma unroll
    for (int nt = 0; nt < 16; nt++) {
        int col = h * DHEAD + nt * 8 + 2 * tg;
        float* o0 = &g_attn[(b * TNEW + r0 + g) * CDIM + col];
        o0[0] = O[nt][0] * i0;
        o0[1] = O[nt][1] * i0;
        float* o1 = &g_attn[(b * TNEW + r0 + g + 8) * CDIM + col];
        o1[0] = O[nt][2] * i1;
        o1[1] = O[nt][3] * i1;
    }
}

// ---------------------------------------------------------------------------
extern "C" void kernel_launch(void* const* d_in, const int* in_sizes, int n_in,
                              void* d_out, int out_size)
{
    const float* x  = (const float*)d_in[0];
    const float* Kp = (const float*)d_in[1];
    const float* Vp = (const float*)d_in[2];
    const float* Wq = (const float*)d_in[3];
    const float* bq = (const float*)d_in[4];
    const float* Wk = (const float*)d_in[5];
    const float* bk = (const float*)d_in[6];
    const float* Wv = (const float*)d_in[7];
    const float* bv = (const float*)d_in[8];
    const float* Wo = (const float*)d_in[9];
    const float* bo = (const float*)d_in[10];

    float* out  = (float*)d_out;
    float* Kout = out + (size_t)M_ROWS * CDIM;
    float* Vout = Kout + (size_t)BATCH * HHEADS * TTOT * DHEAD;

    float *gQ, *gA;
    cudaGetSymbolAddress((void**)&gQ, g_Q);
    cudaGetSymbolAddress((void**)&gA, g_attn);

    const int attn_smem = 3 * 128 * SMS * sizeof(float);  // 202,752 B
    cudaFuncSetAttribute(attn_kernel, cudaFuncAttributeMaxDynamicSharedMemorySize, attn_smem);

    // Phase 1: fused QKV projections + past-KV copy (overlapped in one launch)
    dim3 fg(CDIM / 128, M_ROWS / 128, 4);  // (16, 8, 4)
    fused_qkv_copy<<<fg, 256>>>(x, Wq, bq, Wk, bk, Wv, bv, Kp, Vp, gQ, Kout, Vout);

    // Phase 2: attention
    attn_kernel<<<BATCH * HHEADS, 256, attn_smem>>>(Kout, Vout);

    // Phase 3: output projection
    dim3 gg(CDIM / 128, M_ROWS / 128);  // (16, 8)
    gemm_wo<<<gg, 256>>>(gA, Wo, bo, out);
}